// round 1
// baseline (speedup 1.0000x reference)
#include <cuda_runtime.h>
#include <cuda_bf16.h>
#include <cstdint>

// Problem dims (fixed): enc_out [32,2048,1024] f32, dec_hidden [32,1024],
// Wa [1024,1024], Ua [1024,1024], Va [1024]. Output context [32,1024] f32.
#define BB 32
#define TT 2048
#define HH 1024
#define UU 1024
#define MM (BB * TT)   // 65536

// Scratch (no allocs allowed -> device globals)
__device__ float g_dproj[BB * UU];    // [32][1024]
__device__ float g_score[BB * TT];    // [32][2048], reused for alpha

// ---------------------------------------------------------------------------
// Phase 0: zero scratch
// ---------------------------------------------------------------------------
__global__ void init_kernel() {
    int i = blockIdx.x * blockDim.x + threadIdx.x;
    if (i < BB * UU) g_dproj[i] = 0.0f;
    if (i < BB * TT) g_score[i] = 0.0f;
}

// ---------------------------------------------------------------------------
// Phase 1: dec_proj[b][u] = sum_h dec[b][h] * Wa[h][u]
// grid (8 u-tiles of 128, 4 h-splits of 256, 4 b-groups of 8), 128 threads
// ---------------------------------------------------------------------------
__global__ void dproj_kernel(const float* __restrict__ dec,
                             const float* __restrict__ Wa) {
    const int tid = threadIdx.x;
    const int u   = blockIdx.x * 128 + tid;
    const int h0  = blockIdx.y * 256;
    const int b0  = blockIdx.z * 8;

    __shared__ float sdec[8][256];
    #pragma unroll
    for (int i = 0; i < 16; ++i) {
        int idx = i * 128 + tid;
        int bb = idx >> 8, hh = idx & 255;
        sdec[bb][hh] = dec[(b0 + bb) * HH + h0 + hh];
    }
    __syncthreads();

    float acc[8];
    #pragma unroll
    for (int j = 0; j < 8; ++j) acc[j] = 0.0f;

    #pragma unroll 4
    for (int h = 0; h < 256; ++h) {
        float wa = Wa[(size_t)(h0 + h) * UU + u];
        #pragma unroll
        for (int j = 0; j < 8; ++j) acc[j] += sdec[j][h] * wa;
    }
    #pragma unroll
    for (int j = 0; j < 8; ++j)
        atomicAdd(&g_dproj[(b0 + j) * UU + u], acc[j]);
}

// ---------------------------------------------------------------------------
// Phase 2: fused GEMM + tanh + Va-reduction -> score
// C = enc_out[M,K] @ Ua[K,N]; score[m] += sum_n tanh(C[m,n]+dproj[b][n])*Va[n]
// Block tile 128x128, BK=32, 512 threads (16 warps as 4x4), warp tile 32x32.
// mma.sync.m16n8k8 tf32 (legacy HMMA path).
// ---------------------------------------------------------------------------
__device__ __forceinline__ float f2tf(float f) {
    uint32_t u;
    asm("cvt.rna.tf32.f32 %0, %1;" : "=r"(u) : "f"(f));
    return __uint_as_float(u);
}

__device__ __forceinline__ void mma_tf32(float c[4], const uint32_t a[4],
                                         const uint32_t b[2]) {
    asm volatile(
        "mma.sync.aligned.m16n8k8.row.col.f32.tf32.tf32.f32 "
        "{%0,%1,%2,%3}, {%4,%5,%6,%7}, {%8,%9}, {%0,%1,%2,%3};\n"
        : "+f"(c[0]), "+f"(c[1]), "+f"(c[2]), "+f"(c[3])
        : "r"(a[0]), "r"(a[1]), "r"(a[2]), "r"(a[3]), "r"(b[0]), "r"(b[1]));
}

__global__ void __launch_bounds__(512)
gemm_score_kernel(const float* __restrict__ enc, const float* __restrict__ Ua,
                  const float* __restrict__ Va) {
    __shared__ float As[128][36];     // conflict-free for frag reads
    __shared__ float Bs[32][136];     // 136 -> bank = 8q+8nt+g, conflict-free
    __shared__ float sDp[128];
    __shared__ float sVa[128];

    const int tid = threadIdx.x;
    const int n0 = blockIdx.x * 128;
    const int m0 = blockIdx.y * 128;
    const int b  = m0 >> 11;          // / TT

    if (tid < 128) {
        sDp[tid] = g_dproj[b * UU + n0 + tid];
        sVa[tid] = Va[n0 + tid];
    }

    const int wid = tid >> 5, lane = tid & 31;
    const int wm = wid >> 2, wn = wid & 3;
    const int g = lane >> 2, q = lane & 3;

    // gmem staging coordinates
    const int ar = tid >> 3;            // 0..63 (A rows, +64 for second half)
    const int ac = (tid & 7) << 2;      // A col group (float4)
    const int br = tid >> 5;            // 0..15 (B k-rows, +16 second half)
    const int bc = (tid & 31) << 2;     // B col group (float4)

    const float* Ag = enc + (size_t)m0 * HH;

    float acc[2][4][4];
    #pragma unroll
    for (int i = 0; i < 2; ++i)
        #pragma unroll
        for (int j = 0; j < 4; ++j)
            #pragma unroll
            for (int k = 0; k < 4; ++k) acc[i][j][k] = 0.0f;

    // prologue: stage tile 0
    float4 ra0 = *(const float4*)(Ag + (size_t)ar * HH + ac);
    float4 ra1 = *(const float4*)(Ag + (size_t)(ar + 64) * HH + ac);
    float4 rb0 = *(const float4*)(Ua + (size_t)br * UU + n0 + bc);
    float4 rb1 = *(const float4*)(Ua + (size_t)(br + 16) * UU + n0 + bc);

    for (int kt = 0; kt < 32; ++kt) {
        __syncthreads();
        // store staged tile (converted to tf32 bit patterns)
        As[ar][ac + 0] = f2tf(ra0.x); As[ar][ac + 1] = f2tf(ra0.y);
        As[ar][ac + 2] = f2tf(ra0.z); As[ar][ac + 3] = f2tf(ra0.w);
        As[ar + 64][ac + 0] = f2tf(ra1.x); As[ar + 64][ac + 1] = f2tf(ra1.y);
        As[ar + 64][ac + 2] = f2tf(ra1.z); As[ar + 64][ac + 3] = f2tf(ra1.w);
        Bs[br][bc + 0] = f2tf(rb0.x); Bs[br][bc + 1] = f2tf(rb0.y);
        Bs[br][bc + 2] = f2tf(rb0.z); Bs[br][bc + 3] = f2tf(rb0.w);
        Bs[br + 16][bc + 0] = f2tf(rb1.x); Bs[br + 16][bc + 1] = f2tf(rb1.y);
        Bs[br + 16][bc + 2] = f2tf(rb1.z); Bs[br + 16][bc + 3] = f2tf(rb1.w);
        __syncthreads();

        if (kt < 31) {  // stage next tile (overlaps with MMA below)
            int k0 = (kt + 1) * 32;
            ra0 = *(const float4*)(Ag + (size_t)ar * HH + k0 + ac);
            ra1 = *(const float4*)(Ag + (size_t)(ar + 64) * HH + k0 + ac);
            rb0 = *(const float4*)(Ua + (size_t)(k0 + br) * UU + n0 + bc);
            rb1 = *(const float4*)(Ua + (size_t)(k0 + br + 16) * UU + n0 + bc);
        }

        #pragma unroll
        for (int ks = 0; ks < 4; ++ks) {
            const int kk = ks * 8;
            uint32_t af[2][4];
            #pragma unroll
            for (int mt = 0; mt < 2; ++mt) {
                const int rb_ = wm * 32 + mt * 16;
                af[mt][0] = __float_as_uint(As[rb_ + g][kk + q]);
                af[mt][1] = __float_as_uint(As[rb_ + g + 8][kk + q]);
                af[mt][2] = __float_as_uint(As[rb_ + g][kk + q + 4]);
                af[mt][3] = __float_as_uint(As[rb_ + g + 8][kk + q + 4]);
            }
            uint32_t bf[4][2];
            #pragma unroll
            for (int nt = 0; nt < 4; ++nt) {
                const int cb = wn * 32 + nt * 8 + g;
                bf[nt][0] = __float_as_uint(Bs[kk + q][cb]);
                bf[nt][1] = __float_as_uint(Bs[kk + q + 4][cb]);
            }
            #pragma unroll
            for (int mt = 0; mt < 2; ++mt)
                #pragma unroll
                for (int nt = 0; nt < 4; ++nt)
                    mma_tf32(acc[mt][nt], af[mt], bf[nt]);
        }
    }

    // fused epilogue: score[m] += sum_n tanh(acc + dproj[n]) * Va[n]
    float rs[2][2] = {{0.0f, 0.0f}, {0.0f, 0.0f}};
    #pragma unroll
    for (int mt = 0; mt < 2; ++mt) {
        #pragma unroll
        for (int nt = 0; nt < 4; ++nt) {
            const int nb = wn * 32 + nt * 8 + (q << 1);
            const float dp0 = sDp[nb],     va0 = sVa[nb];
            const float dp1 = sDp[nb + 1], va1 = sVa[nb + 1];
            rs[mt][0] += tanhf(acc[mt][nt][0] + dp0) * va0
                       + tanhf(acc[mt][nt][1] + dp1) * va1;
            rs[mt][1] += tanhf(acc[mt][nt][2] + dp0) * va0
                       + tanhf(acc[mt][nt][3] + dp1) * va1;
        }
    }
    #pragma unroll
    for (int mt = 0; mt < 2; ++mt) {
        #pragma unroll
        for (int r = 0; r < 2; ++r) {
            float v = rs[mt][r];
            v += __shfl_xor_sync(0xffffffffu, v, 1);
            v += __shfl_xor_sync(0xffffffffu, v, 2);
            if (q == 0)
                atomicAdd(&g_score[m0 + wm * 32 + mt * 16 + (r << 3) + g], v);
        }
    }
}

// ---------------------------------------------------------------------------
// Phase 3: softmax over T per batch (in-place on g_score)
// ---------------------------------------------------------------------------
__global__ void softmax_kernel() {
    const int bb = blockIdx.x, tid = threadIdx.x;
    __shared__ float red[256];
    float* s = g_score + bb * TT;

    float m = -1e30f;
    for (int t = tid; t < TT; t += 256) m = fmaxf(m, s[t]);
    red[tid] = m; __syncthreads();
    for (int o = 128; o > 0; o >>= 1) {
        if (tid < o) red[tid] = fmaxf(red[tid], red[tid + o]);
        __syncthreads();
    }
    m = red[0]; __syncthreads();

    float sum = 0.0f;
    for (int t = tid; t < TT; t += 256) {
        float e = __expf(s[t] - m);
        s[t] = e;
        sum += e;
    }
    red[tid] = sum; __syncthreads();
    for (int o = 128; o > 0; o >>= 1) {
        if (tid < o) red[tid] += red[tid + o];
        __syncthreads();
    }
    const float inv = 1.0f / red[0];
    for (int t = tid; t < TT; t += 256) s[t] *= inv;
}

// ---------------------------------------------------------------------------
// Phase 4: context[b][h] = sum_t alpha[b][t] * enc[b][t][h]
// grid (4 h-chunks, 32 b), 256 threads; no atomics, fully coalesced stream.
// ---------------------------------------------------------------------------
__global__ void context_kernel(const float* __restrict__ enc,
                               float* __restrict__ out) {
    const int bb = blockIdx.y;
    const int h = blockIdx.x * 256 + threadIdx.x;
    __shared__ float sal[TT];
    for (int t = threadIdx.x; t < TT; t += 256) sal[t] = g_score[bb * TT + t];
    __syncthreads();

    const float* e = enc + (size_t)bb * TT * HH + h;
    float acc = 0.0f;
    #pragma unroll 8
    for (int t = 0; t < TT; ++t) acc += sal[t] * e[(size_t)t * HH];
    out[bb * HH + h] = acc;
}

// ---------------------------------------------------------------------------
extern "C" void kernel_launch(void* const* d_in, const int* in_sizes, int n_in,
                              void* d_out, int out_size) {
    const float* enc = (const float*)d_in[0];
    const float* dec = (const float*)d_in[1];
    const float* Wa  = (const float*)d_in[2];
    const float* Ua  = (const float*)d_in[3];
    const float* Va  = (const float*)d_in[4];
    float* out = (float*)d_out;

    init_kernel<<<64, 1024>>>();
    dproj_kernel<<<dim3(8, 4, 4), 128>>>(dec, Wa);
    gemm_score_kernel<<<dim3(UU / 128, MM / 128), 512>>>(enc, Ua, Va);
    softmax_kernel<<<BB, 256>>>();
    context_kernel<<<dim3(HH / 256, BB), 256>>>(enc, out);
}

// round 3
// speedup vs baseline: 2.1247x; 2.1247x over previous
#include <cuda_runtime.h>
#include <cuda_bf16.h>
#include <cstdint>

// Problem dims (fixed): enc_out [32,2048,1024] f32, dec_hidden [32,1024],
// Wa [1024,1024], Ua [1024,1024], Va [1024]. Output context [32,1024] f32.
#define BB 32
#define TT 2048
#define HH 1024
#define UU 1024
#define MM (BB * TT)   // 65536

// Scratch (no allocs allowed -> device globals)
__device__ float g_dproj[BB * UU];     // [32][1024]
__device__ float g_score[BB * TT];     // [32][2048], reused for alpha

// ---------------------------------------------------------------------------
// Helpers (sm_90-base-safe only: cp.async, mma.sync tf32, shfl)
// ---------------------------------------------------------------------------
__device__ __forceinline__ uint32_t smem_u32(const void* p) {
    uint32_t a;
    asm("{ .reg .u64 t; cvta.to.shared.u64 t, %1; cvt.u32.u64 %0, t; }"
        : "=r"(a) : "l"(p));
    return a;
}

__device__ __forceinline__ void cp16(uint32_t saddr, const float* g) {
    asm volatile("cp.async.cg.shared.global [%0], [%1], 16;"
                 :: "r"(saddr), "l"(g) : "memory");
}
#define CP_COMMIT() asm volatile("cp.async.commit_group;" ::: "memory")
#define CP_WAIT(n)  asm volatile("cp.async.wait_group %0;" :: "n"(n) : "memory")

__device__ __forceinline__ void mma_tf32(float c[4], const uint32_t a[4],
                                         const uint32_t b[2]) {
    asm volatile(
        "mma.sync.aligned.m16n8k8.row.col.f32.tf32.tf32.f32 "
        "{%0,%1,%2,%3}, {%4,%5,%6,%7}, {%8,%9}, {%0,%1,%2,%3};\n"
        : "+f"(c[0]), "+f"(c[1]), "+f"(c[2]), "+f"(c[3])
        : "r"(a[0]), "r"(a[1]), "r"(a[2]), "r"(a[3]), "r"(b[0]), "r"(b[1]));
}

__device__ __forceinline__ float fast_tanh(float x) {
    float e, r;
    asm("ex2.approx.f32 %0, %1;" : "=f"(e) : "f"(x * 2.8853900817779268f));
    asm("rcp.approx.f32 %0, %1;" : "=f"(r) : "f"(e + 1.0f));
    return __fmaf_rn(-2.0f, r, 1.0f);
}

// ---------------------------------------------------------------------------
// Phase 0: zero scratch + output
// ---------------------------------------------------------------------------
__global__ void init_kernel(float* out) {
    int i = blockIdx.x * blockDim.x + threadIdx.x;
    if (i < BB * UU) g_dproj[i] = 0.0f;
    if (i < BB * TT) g_score[i] = 0.0f;
    if (i < BB * HH) out[i] = 0.0f;
}

// ---------------------------------------------------------------------------
// Phase 1: dec_proj[b][u] = sum_h dec[b][h] * Wa[h][u]
// ---------------------------------------------------------------------------
__global__ void dproj_kernel(const float* __restrict__ dec,
                             const float* __restrict__ Wa) {
    const int tid = threadIdx.x;
    const int u   = blockIdx.x * 128 + tid;
    const int h0  = blockIdx.y * 256;
    const int b0  = blockIdx.z * 8;

    __shared__ float sdec[8][256];
    #pragma unroll
    for (int i = 0; i < 16; ++i) {
        int idx = i * 128 + tid;
        sdec[idx >> 8][idx & 255] = dec[(b0 + (idx >> 8)) * HH + h0 + (idx & 255)];
    }
    __syncthreads();

    float acc[8];
    #pragma unroll
    for (int j = 0; j < 8; ++j) acc[j] = 0.0f;
    #pragma unroll 4
    for (int h = 0; h < 256; ++h) {
        float wa = Wa[(size_t)(h0 + h) * UU + u];
        #pragma unroll
        for (int j = 0; j < 8; ++j) acc[j] += sdec[j][h] * wa;
    }
    #pragma unroll
    for (int j = 0; j < 8; ++j)
        atomicAdd(&g_dproj[(b0 + j) * UU + u], acc[j]);
}

// ---------------------------------------------------------------------------
// Phase 2: tf32 legacy-MMA GEMM, fused tanh + Va-reduce -> g_score
// Block tile 128(M) x 256(N), BK=32, 256 threads (8 warps as 2x4),
// warp tile 64x64 (mt=4, nt=8). 3-stage cp.async pipeline.
// SMEM per stage: A [128][36] floats (18432B) + B [32][264] floats (33792B).
// A pitch 36, B pitch 264 -> fragment LDS conflict-free, rows 16B-aligned.
// HW truncates fp32->tf32 on operand read (no cvt needed).
// ---------------------------------------------------------------------------
#define APITCH 36
#define BPITCH 264
#define A_BYTES (128 * APITCH * 4)               // 18432
#define STAGE_BYTES (A_BYTES + 32 * BPITCH * 4)  // 52224
#define NSTAGE 3
#define GEMM_SMEM (NSTAGE * STAGE_BYTES)         // 156672

__device__ __forceinline__ void stage_load(uint32_t sbase, int s,
                                           const float* __restrict__ enc,
                                           const float* __restrict__ Ua,
                                           int m0, int n0, int kt, int tid) {
    const uint32_t st = sbase + s * STAGE_BYTES;
    // A: 128 rows x 32 floats = 1024 x 16B, 4 per thread
    #pragma unroll
    for (int j = 0; j < 4; ++j) {
        int idx = j * 256 + tid;
        int row = idx >> 3, grp = idx & 7;
        cp16(st + row * (APITCH * 4) + grp * 16,
             enc + (size_t)(m0 + row) * HH + kt * 32 + grp * 4);
    }
    // B: 32 k-rows x 256 floats = 2048 x 16B, 8 per thread
    #pragma unroll
    for (int j = 0; j < 8; ++j) {
        int idx = j * 256 + tid;
        int krow = idx >> 6, grp = idx & 63;
        cp16(st + A_BYTES + krow * (BPITCH * 4) + grp * 16,
             Ua + (size_t)(kt * 32 + krow) * UU + n0 + grp * 4);
    }
    CP_COMMIT();
}

__global__ void __launch_bounds__(256, 1)
gemm_score_kernel(const float* __restrict__ enc, const float* __restrict__ Ua,
                  const float* __restrict__ Va) {
    extern __shared__ char smem[];
    __shared__ float sDp[256];
    __shared__ float sVa[256];
    const uint32_t sb = smem_u32(smem);

    const int tid = threadIdx.x;
    const int n0 = blockIdx.x * 256;
    const int m0 = blockIdx.y * 128;
    const int b  = m0 >> 11;

    sDp[tid] = g_dproj[b * UU + n0 + tid];
    sVa[tid] = Va[n0 + tid];

    const int wid = tid >> 5, lane = tid & 31;
    const int wm = wid >> 2, wn = wid & 3;     // 2 x 4 warps
    const int g = lane >> 2, q = lane & 3;

    float acc[4][8][4];
    #pragma unroll
    for (int i = 0; i < 4; ++i)
        #pragma unroll
        for (int j = 0; j < 8; ++j)
            #pragma unroll
            for (int k = 0; k < 4; ++k) acc[i][j][k] = 0.0f;

    // prologue: stages 0, 1
    stage_load(sb, 0, enc, Ua, m0, n0, 0, tid);
    stage_load(sb, 1, enc, Ua, m0, n0, 1, tid);

    for (int kt = 0; kt < 32; ++kt) {
        if (kt + 2 < 32)
            stage_load(sb, (kt + 2) % NSTAGE, enc, Ua, m0, n0, kt + 2, tid);
        if (kt < 30)       CP_WAIT(2);
        else if (kt == 30) CP_WAIT(1);
        else               CP_WAIT(0);
        __syncthreads();

        const float* As = (const float*)(smem + (kt % NSTAGE) * STAGE_BYTES);
        const float* Bs = (const float*)(smem + (kt % NSTAGE) * STAGE_BYTES + A_BYTES);

        #pragma unroll
        for (int ks = 0; ks < 4; ++ks) {
            const int kk = ks * 8;
            uint32_t af[4][4];
            #pragma unroll
            for (int mt = 0; mt < 4; ++mt) {
                const int rb_ = wm * 64 + mt * 16;
                af[mt][0] = __float_as_uint(As[(rb_ + g) * APITCH + kk + q]);
                af[mt][1] = __float_as_uint(As[(rb_ + g + 8) * APITCH + kk + q]);
                af[mt][2] = __float_as_uint(As[(rb_ + g) * APITCH + kk + q + 4]);
                af[mt][3] = __float_as_uint(As[(rb_ + g + 8) * APITCH + kk + q + 4]);
            }
            uint32_t bf[8][2];
            #pragma unroll
            for (int nt = 0; nt < 8; ++nt) {
                const int cb = wn * 64 + nt * 8 + g;
                bf[nt][0] = __float_as_uint(Bs[(kk + q) * BPITCH + cb]);
                bf[nt][1] = __float_as_uint(Bs[(kk + q + 4) * BPITCH + cb]);
            }
            #pragma unroll
            for (int mt = 0; mt < 4; ++mt)
                #pragma unroll
                for (int nt = 0; nt < 8; ++nt)
                    mma_tf32(acc[mt][nt], af[mt], bf[nt]);
        }
        __syncthreads();
    }

    // fused epilogue: score[m] += sum_n tanh(acc + dproj[n]) * Va[n]
    #pragma unroll
    for (int mt = 0; mt < 4; ++mt) {
        float rs[2] = {0.0f, 0.0f};
        #pragma unroll
        for (int nt = 0; nt < 8; ++nt) {
            const int nb = wn * 64 + nt * 8 + (q << 1);
            const float dp0 = sDp[nb],     va0 = sVa[nb];
            const float dp1 = sDp[nb + 1], va1 = sVa[nb + 1];
            rs[0] += fast_tanh(acc[mt][nt][0] + dp0) * va0
                   + fast_tanh(acc[mt][nt][1] + dp1) * va1;
            rs[1] += fast_tanh(acc[mt][nt][2] + dp0) * va0
                   + fast_tanh(acc[mt][nt][3] + dp1) * va1;
        }
        #pragma unroll
        for (int r = 0; r < 2; ++r) {
            float v = rs[r];
            v += __shfl_xor_sync(0xffffffffu, v, 1);
            v += __shfl_xor_sync(0xffffffffu, v, 2);
            if (q == 0)
                atomicAdd(&g_score[m0 + wm * 64 + mt * 16 + (r << 3) + g], v);
        }
    }
}

// ---------------------------------------------------------------------------
// Phase 3: softmax over T per batch (in-place on g_score)
// ---------------------------------------------------------------------------
__global__ void softmax_kernel() {
    const int bb = blockIdx.x, tid = threadIdx.x;
    __shared__ float red[256];
    float* s = g_score + bb * TT;

    float m = -1e30f;
    for (int t = tid; t < TT; t += 256) m = fmaxf(m, s[t]);
    red[tid] = m; __syncthreads();
    for (int o = 128; o > 0; o >>= 1) {
        if (tid < o) red[tid] = fmaxf(red[tid], red[tid + o]);
        __syncthreads();
    }
    m = red[0]; __syncthreads();

    float sum = 0.0f;
    for (int t = tid; t < TT; t += 256) {
        float e = __expf(s[t] - m);
        s[t] = e;
        sum += e;
    }
    red[tid] = sum; __syncthreads();
    for (int o = 128; o > 0; o >>= 1) {
        if (tid < o) red[tid] += red[tid + o];
        __syncthreads();
    }
    const float inv = 1.0f / red[0];
    for (int t = tid; t < TT; t += 256) s[t] *= inv;
}

// ---------------------------------------------------------------------------
// Phase 4: context[b][h] = sum_t alpha[b][t]*enc[b][t][h]; T split x4, atomics
// ---------------------------------------------------------------------------
__global__ void context_kernel(const float* __restrict__ enc,
                               float* __restrict__ out) {
    const int bb = blockIdx.y;
    const int ts = blockIdx.z * 512;
    const int h  = blockIdx.x * 256 + threadIdx.x;
    __shared__ float sal[512];
    sal[threadIdx.x]       = g_score[bb * TT + ts + threadIdx.x];
    sal[threadIdx.x + 256] = g_score[bb * TT + ts + threadIdx.x + 256];
    __syncthreads();

    const float* e = enc + (size_t)bb * TT * HH + (size_t)ts * HH + h;
    float acc = 0.0f;
    #pragma unroll 8
    for (int t = 0; t < 512; ++t) acc += sal[t] * e[(size_t)t * HH];
    atomicAdd(&out[bb * HH + h], acc);
}

// ---------------------------------------------------------------------------
extern "C" void kernel_launch(void* const* d_in, const int* in_sizes, int n_in,
                              void* d_out, int out_size) {
    const float* enc = (const float*)d_in[0];
    const float* dec = (const float*)d_in[1];
    const float* Wa  = (const float*)d_in[2];
    const float* Ua  = (const float*)d_in[3];
    const float* Va  = (const float*)d_in[4];
    float* out = (float*)d_out;

    cudaFuncSetAttribute(gemm_score_kernel,
                         cudaFuncAttributeMaxDynamicSharedMemorySize, GEMM_SMEM);

    init_kernel<<<64, 1024>>>(out);
    dproj_kernel<<<dim3(8, 4, 4), 128>>>(dec, Wa);
    gemm_score_kernel<<<dim3(UU / 256, MM / 128), 256, GEMM_SMEM>>>(enc, Ua, Va);
    softmax_kernel<<<BB, 256>>>();
    context_kernel<<<dim3(HH / 256, BB, TT / 512), 256>>>(enc, out);
}

// round 7
// speedup vs baseline: 2.5024x; 1.1778x over previous
#include <cuda_runtime.h>
#include <cuda_bf16.h>
#include <cstdint>

// Problem dims (fixed): enc_out [32,2048,1024] f32, dec_hidden [32,1024],
// Wa [1024,1024], Ua [1024,1024], Va [1024]. Output context [32,1024] f32.
#define BB 32
#define TT 2048
#define HH 1024
#define UU 1024
#define MM (BB * TT)   // 65536

// Scratch (no allocs allowed -> device globals)
__device__ float g_dproj[BB * UU];     // [32][1024]
__device__ float g_score[BB * TT];     // [32][2048], reused for alpha

// ---------------------------------------------------------------------------
// Helpers (base-sm_103-safe: cp.async, mbarrier, mma.sync tf32)
// ---------------------------------------------------------------------------
__device__ __forceinline__ uint32_t smem_u32(const void* p) {
    uint32_t a;
    asm("{ .reg .u64 t; cvta.to.shared.u64 t, %1; cvt.u32.u64 %0, t; }"
        : "=r"(a) : "l"(p));
    return a;
}

__device__ __forceinline__ void cp16(uint32_t saddr, const float* g) {
    asm volatile("cp.async.cg.shared.global [%0], [%1], 16;"
                 :: "r"(saddr), "l"(g) : "memory");
}

#define MBAR_INIT(addr, cnt) \
    asm volatile("mbarrier.init.shared.b64 [%0], %1;" :: "r"(addr), "r"(cnt) : "memory")

#define MBAR_ARRIVE(addr) \
    asm volatile("mbarrier.arrive.shared.b64 _, [%0];" :: "r"(addr) : "memory")

// NOTE: .noinc is load-bearing. Without it, each call bumps the pending count
// by 1 before the deferred arrive (net zero) and the barrier never flips
// (round-5 deadlock). With .noinc, each producer thread's completed cp.async
// group is a plain arrival: 64 arrivals/phase == init count.
#define MBAR_ARRIVE_CP_NOINC(addr) \
    asm volatile("cp.async.mbarrier.arrive.noinc.shared::cta.b64 [%0];" :: "r"(addr) : "memory")

#define MBAR_WAIT(addr, par) do {                                              \
    uint32_t _m = (addr), _p = (par), _d;                                      \
    asm volatile("{\n\t.reg .pred p;\n\t"                                      \
        "mbarrier.try_wait.parity.acquire.cta.shared::cta.b64 p, [%1], %2;\n\t" \
        "selp.b32 %0, 1, 0, p;\n\t}"                                           \
        : "=r"(_d) : "r"(_m), "r"(_p) : "memory");                             \
    if (!_d) {                                                                 \
        asm volatile("{\n\t.reg .pred P1;\n\t"                                 \
            "W_%=:\n\t"                                                        \
            "mbarrier.try_wait.parity.acquire.cta.shared::cta.b64 P1, [%0], %1, 0x989680;\n\t" \
            "@P1 bra.uni D_%=;\n\t"                                            \
            "bra.uni W_%=;\n\t"                                                \
            "D_%=:\n\t}" :: "r"(_m), "r"(_p) : "memory");                      \
    }                                                                          \
} while (0)

__device__ __forceinline__ void mma_tf32(float c[4], const uint32_t a[4],
                                         const uint32_t b[2]) {
    asm volatile(
        "mma.sync.aligned.m16n8k8.row.col.f32.tf32.tf32.f32 "
        "{%0,%1,%2,%3}, {%4,%5,%6,%7}, {%8,%9}, {%0,%1,%2,%3};\n"
        : "+f"(c[0]), "+f"(c[1]), "+f"(c[2]), "+f"(c[3])
        : "r"(a[0]), "r"(a[1]), "r"(a[2]), "r"(a[3]), "r"(b[0]), "r"(b[1]));
}

__device__ __forceinline__ float fast_tanh(float x) {
    float e, r;
    asm("ex2.approx.f32 %0, %1;" : "=f"(e) : "f"(x * 2.8853900817779268f));
    asm("rcp.approx.f32 %0, %1;" : "=f"(r) : "f"(e + 1.0f));
    return __fmaf_rn(-2.0f, r, 1.0f);
}

// ---------------------------------------------------------------------------
// Phase 0: zero scratch + output;  dummy: ncu launch-slot alignment
// ---------------------------------------------------------------------------
__global__ void init_kernel(float* out) {
    int i = blockIdx.x * blockDim.x + threadIdx.x;
    if (i < BB * UU) g_dproj[i] = 0.0f;
    if (i < BB * TT) g_score[i] = 0.0f;
    if (i < BB * HH) out[i] = 0.0f;
}
__global__ void dummy_kernel() {}

// ---------------------------------------------------------------------------
// Phase 1: dec_proj[b][u] = sum_h dec[b][h] * Wa[h][u]
// ---------------------------------------------------------------------------
__global__ void dproj_kernel(const float* __restrict__ dec,
                             const float* __restrict__ Wa) {
    const int tid = threadIdx.x;
    const int u   = blockIdx.x * 128 + tid;
    const int h0  = blockIdx.y * 256;
    const int b0  = blockIdx.z * 8;

    __shared__ float sdec[8][256];
    #pragma unroll
    for (int i = 0; i < 16; ++i) {
        int idx = i * 128 + tid;
        sdec[idx >> 8][idx & 255] = dec[(b0 + (idx >> 8)) * HH + h0 + (idx & 255)];
    }
    __syncthreads();

    float acc[8];
    #pragma unroll
    for (int j = 0; j < 8; ++j) acc[j] = 0.0f;
    #pragma unroll 4
    for (int h = 0; h < 256; ++h) {
        float wa = Wa[(size_t)(h0 + h) * UU + u];
        #pragma unroll
        for (int j = 0; j < 8; ++j) acc[j] += sdec[j][h] * wa;
    }
    #pragma unroll
    for (int j = 0; j < 8; ++j)
        atomicAdd(&g_dproj[(b0 + j) * UU + u], acc[j]);
}

// ---------------------------------------------------------------------------
// Phase 2: warp-specialized tf32 MMA GEMM, fused tanh + Va-reduce -> g_score
// Block tile 128(M) x 256(N). BK=16, 4-stage mbarrier ring, NO __syncthreads
// in the mainloop. 320 threads: warps 0-7 consumers (2x4 grid, 64x64 warp
// tile), warps 8-9 producers (cp.async).
// Stage: A 128 rows x 16 floats, pitch 20 (10240B) + B 16 rows x 256 floats,
// pitch 264 (16896B) = 27136B. Fragment LDS conflict-free for both.
// ---------------------------------------------------------------------------
#define NSTAGE 4
#define BK 16
#define APITCH 20
#define BPITCH 264
#define A_BYTES (128 * APITCH * 4)                 // 10240
#define STAGE_BYTES (A_BYTES + BK * BPITCH * 4)    // 27136
#define SDP_OFF 128
#define SVA_OFF 1152
#define STAGE0 2176
#define GEMM_SMEM (STAGE0 + NSTAGE * STAGE_BYTES)  // 110720
#define NCHUNK (HH / BK)                            // 64

__global__ void __launch_bounds__(320, 1)
gemm_score_kernel(const float* __restrict__ enc, const float* __restrict__ Ua,
                  const float* __restrict__ Va) {
    extern __shared__ char smem[];
    const uint32_t sb = smem_u32(smem);
    const int tid = threadIdx.x;

    const int n0 = blockIdx.x * 256;
    const int m0 = blockIdx.y * 128;
    const int b  = m0 >> 11;

    if (tid == 0) {
        #pragma unroll
        for (int s = 0; s < NSTAGE; ++s) {
            MBAR_INIT(sb + s * 8, 64);        // full: 64 producer cp-arrivals
            MBAR_INIT(sb + 32 + s * 8, 256);  // empty: 256 consumer arrivals
        }
    }
    if (tid < 256) {
        ((float*)(smem + SDP_OFF))[tid] = g_dproj[b * UU + n0 + tid];
        ((float*)(smem + SVA_OFF))[tid] = Va[n0 + tid];
    }
    __syncthreads();

    if (tid >= 256) {
        // ======================= producers (warps 8-9) =======================
        const int pt = tid - 256;  // 0..63
        for (int c = 0; c < NCHUNK; ++c) {
            const int s = c & 3;
            if (c >= NSTAGE) MBAR_WAIT(sb + 32 + s * 8, ((c >> 2) - 1) & 1);
            const uint32_t st = sb + STAGE0 + s * STAGE_BYTES;
            const float* gA = enc + (size_t)m0 * HH + c * BK;
            #pragma unroll
            for (int j = 0; j < 8; ++j) {
                int idx = j * 64 + pt;
                int row = idx >> 2, grp = idx & 3;
                cp16(st + row * (APITCH * 4) + grp * 16,
                     gA + (size_t)row * HH + grp * 4);
            }
            const float* gB = Ua + (size_t)(c * BK) * UU + n0;
            #pragma unroll
            for (int j = 0; j < 16; ++j) {
                int idx = j * 64 + pt;
                int kr = idx >> 6, grp = idx & 63;
                cp16(st + A_BYTES + kr * (BPITCH * 4) + grp * 16,
                     gB + (size_t)kr * UU + grp * 4);
            }
            MBAR_ARRIVE_CP_NOINC(sb + s * 8);
        }
        return;
    }

    // ======================== consumers (warps 0-7) ==========================
    const int wid = tid >> 5, lane = tid & 31;
    const int wm = wid >> 2, wn = wid & 3;     // 2 x 4 warps
    const int g = lane >> 2, q = lane & 3;

    float acc[4][8][4];
    #pragma unroll
    for (int i = 0; i < 4; ++i)
        #pragma unroll
        for (int j = 0; j < 8; ++j)
            #pragma unroll
            for (int k = 0; k < 4; ++k) acc[i][j][k] = 0.0f;

    for (int c = 0; c < NCHUNK; ++c) {
        const int s = c & 3;
        MBAR_WAIT(sb + s * 8, (c >> 2) & 1);
        const float* As = (const float*)(smem + STAGE0 + s * STAGE_BYTES);
        const float* Bs = (const float*)(smem + STAGE0 + s * STAGE_BYTES + A_BYTES);

        #pragma unroll
        for (int ks = 0; ks < 2; ++ks) {
            const int kk = ks * 8;
            uint32_t af[4][4];
            #pragma unroll
            for (int mt = 0; mt < 4; ++mt) {
                const int rb_ = wm * 64 + mt * 16;
                af[mt][0] = __float_as_uint(As[(rb_ + g) * APITCH + kk + q]);
                af[mt][1] = __float_as_uint(As[(rb_ + g + 8) * APITCH + kk + q]);
                af[mt][2] = __float_as_uint(As[(rb_ + g) * APITCH + kk + q + 4]);
                af[mt][3] = __float_as_uint(As[(rb_ + g + 8) * APITCH + kk + q + 4]);
            }
            uint32_t bf[8][2];
            #pragma unroll
            for (int nt = 0; nt < 8; ++nt) {
                const int cb = wn * 64 + nt * 8 + g;
                bf[nt][0] = __float_as_uint(Bs[(kk + q) * BPITCH + cb]);
                bf[nt][1] = __float_as_uint(Bs[(kk + q + 4) * BPITCH + cb]);
            }
            #pragma unroll
            for (int mt = 0; mt < 4; ++mt)
                #pragma unroll
                for (int nt = 0; nt < 8; ++nt)
                    mma_tf32(acc[mt][nt], af[mt], bf[nt]);
        }
        MBAR_ARRIVE(sb + 32 + s * 8);
    }

    // fused epilogue: score[m] += sum_n tanh(acc + dproj[n]) * Va[n]
    const float* dp = (const float*)(smem + SDP_OFF);
    const float* va = (const float*)(smem + SVA_OFF);
    #pragma unroll
    for (int mt = 0; mt < 4; ++mt) {
        float rs[2] = {0.0f, 0.0f};
        #pragma unroll
        for (int nt = 0; nt < 8; ++nt) {
            const int nb = wn * 64 + nt * 8 + (q << 1);
            const float dp0 = dp[nb],     va0 = va[nb];
            const float dp1 = dp[nb + 1], va1 = va[nb + 1];
            rs[0] += fast_tanh(acc[mt][nt][0] + dp0) * va0
                   + fast_tanh(acc[mt][nt][1] + dp1) * va1;
            rs[1] += fast_tanh(acc[mt][nt][2] + dp0) * va0
                   + fast_tanh(acc[mt][nt][3] + dp1) * va1;
        }
        #pragma unroll
        for (int r = 0; r < 2; ++r) {
            float v = rs[r];
            v += __shfl_xor_sync(0xffffffffu, v, 1);
            v += __shfl_xor_sync(0xffffffffu, v, 2);
            if (q == 0)
                atomicAdd(&g_score[m0 + wm * 64 + mt * 16 + (r << 3) + g], v);
        }
    }
}

// ---------------------------------------------------------------------------
// Phase 3: softmax over T per batch (in-place on g_score)
// ---------------------------------------------------------------------------
__global__ void softmax_kernel() {
    const int bb = blockIdx.x, tid = threadIdx.x;
    __shared__ float red[256];
    float* s = g_score + bb * TT;

    float m = -1e30f;
    for (int t = tid; t < TT; t += 256) m = fmaxf(m, s[t]);
    red[tid] = m; __syncthreads();
    for (int o = 128; o > 0; o >>= 1) {
        if (tid < o) red[tid] = fmaxf(red[tid], red[tid + o]);
        __syncthreads();
    }
    m = red[0]; __syncthreads();

    float sum = 0.0f;
    for (int t = tid; t < TT; t += 256) {
        float e = __expf(s[t] - m);
        s[t] = e;
        sum += e;
    }
    red[tid] = sum; __syncthreads();
    for (int o = 128; o > 0; o >>= 1) {
        if (tid < o) red[tid] += red[tid + o];
        __syncthreads();
    }
    const float inv = 1.0f / red[0];
    for (int t = tid; t < TT; t += 256) s[t] *= inv;
}

// ---------------------------------------------------------------------------
// Phase 4: context[b][h] = sum_t alpha[b][t]*enc[b][t][h]; T split x4, atomics
// ---------------------------------------------------------------------------
__global__ void context_kernel(const float* __restrict__ enc,
                               float* __restrict__ out) {
    const int bb = blockIdx.y;
    const int ts = blockIdx.z * 512;
    const int h  = blockIdx.x * 256 + threadIdx.x;
    __shared__ float sal[512];
    sal[threadIdx.x]       = g_score[bb * TT + ts + threadIdx.x];
    sal[threadIdx.x + 256] = g_score[bb * TT + ts + threadIdx.x + 256];
    __syncthreads();

    const float* e = enc + (size_t)bb * TT * HH + (size_t)ts * HH + h;
    float acc = 0.0f;
    #pragma unroll 8
    for (int t = 0; t < 512; ++t) acc += sal[t] * e[(size_t)t * HH];
    atomicAdd(&out[bb * HH + h], acc);
}

// ---------------------------------------------------------------------------
extern "C" void kernel_launch(void* const* d_in, const int* in_sizes, int n_in,
                              void* d_out, int out_size) {
    const float* enc = (const float*)d_in[0];
    const float* dec = (const float*)d_in[1];
    const float* Wa  = (const float*)d_in[2];
    const float* Ua  = (const float*)d_in[3];
    const float* Va  = (const float*)d_in[4];
    float* out = (float*)d_out;

    cudaFuncSetAttribute(gemm_score_kernel,
                         cudaFuncAttributeMaxDynamicSharedMemorySize, GEMM_SMEM);

    init_kernel<<<64, 1024>>>(out);                       // in-call idx 0
    dproj_kernel<<<dim3(8, 4, 4), 128>>>(dec, Wa);        // idx 1
    dummy_kernel<<<1, 32>>>();                            // idx 2 (ncu align)
    gemm_score_kernel<<<dim3(UU / 256, MM / 128), 320, GEMM_SMEM>>>(enc, Ua, Va); // idx 3
    softmax_kernel<<<BB, 256>>>();                        // idx 4
    context_kernel<<<dim3(HH / 256, BB, TT / 512), 256>>>(enc, out); // idx 5
}